// round 10
// baseline (speedup 1.0000x reference)
#include <cuda_runtime.h>
#include <stdint.h>

#define DW    32
#define K2D   64
#define NW    512
#define BATCH 2048
#define PA    36     // wA pitch in float4 (36%8==4 -> conflict-free LDS.128)
#define PX    132    // xs pitch in float2 (conflict-free LDS.64 per half-warp phase)

__device__ __forceinline__ uint32_t tf32_hi(float x) {
    uint32_t r; asm("cvt.rna.tf32.f32 %0, %1;" : "=r"(r) : "f"(x)); return r;
}
__device__ __forceinline__ float tf32_lo(float x, uint32_t h) {
    return __uint_as_float(tf32_hi(x - __uint_as_float(h)));
}

// D += A(tf32)*B(tf32), m16n8k8, A row-major, B col-major
#define HMMA(d, A0, A1, A2, A3, B0, B1) \
    asm volatile("mma.sync.aligned.m16n8k8.row.col.f32.tf32.tf32.f32 " \
        "{%0,%1,%2,%3}, {%4,%5,%6,%7}, {%8,%9}, {%0,%1,%2,%3};" \
        : "+f"((d)[0]), "+f"((d)[1]), "+f"((d)[2]), "+f"((d)[3]) \
        : "r"(A0), "r"(A1), "r"(A2), "r"(A3), "r"(B0), "r"(B1))

__global__ __launch_bounds__(128, 6)
void binop_mma_kernel(const float* __restrict__ states,   // [8*2048, 32, 512]
                      const float* __restrict__ W,        // [128, 32, 64]
                      const float* __restrict__ b,        // [128, 32]
                      const int*   __restrict__ indices,  // [2048]
                      const int*   __restrict__ symbols,  // [2048]
                      const int*   __restrict__ args,     // [2048, 2]
                      float*       __restrict__ out)      // [2048, 32, 512]
{
    // wA[d][ks*4+tig] = {wh(k0), wl(k0), wh(k1), wl(k1)}, k0=ks*8+tig, k1=k0+4
    __shared__ __align__(16) float4 wA[DW * PA];          // 18 KB
    // xs[buf][kk*PX + n] = {xh, xl} for local k-row kk (0..7), world n (0..127)
    __shared__ __align__(16) float2 xs[2][8 * PX];        // 16.9 KB
    __shared__ float bsh[DW];

    const int n    = blockIdx.x >> 2;   // sample
    const int q    = blockIdx.x & 3;    // world quarter (128 worlds)
    const int t    = threadIdx.x;
    const int lane = t & 31;
    const int warp = t >> 5;
    const int g    = lane >> 2;
    const int tig  = lane & 3;

    const int idx = indices[n];
    const int sym = symbols[n];
    const int a0  = args[2 * n];
    const int a1  = args[2 * n + 1];

    // --- W[sym] hi/lo split into packed-pair smem ---
    const float* Wp = W + (size_t)sym * (DW * K2D);
    #pragma unroll
    for (int i = 0; i < 16; i++) {
        int j  = t + 128 * i;           // 0..2047
        int r  = j >> 6;
        int kk = j & 63;
        int ks = kk >> 3, u = kk & 7, pr = u & 3, hf = u >> 2;
        float w  = Wp[j];
        uint32_t h = tf32_hi(w);
        float   lo = tf32_lo(w, h);
        float* dst = (float*)&wA[r * PA + ks * 4 + pr];
        dst[hf * 2]     = __uint_as_float(h);
        dst[hf * 2 + 1] = lo;
    }
    if (t < DW) bsh[t] = b[sym * DW + t];

    const float* xl = states + (size_t)(a0 * BATCH + idx) * (DW * NW) + q * 128;
    const float* xr = states + (size_t)(a1 * BATCH + idx) * (DW * NW) + q * 128;

    const int krow = t >> 5;            // this thread's staging rows (krow, krow+4)
    const int wcol = (t & 31) * 4;      // staging world base

    // load chunk c (global k rows 8c..8c+7) into regs
    #define LDCHUNK(c_, v0_, v1_) do { \
        const float* s_ = ((c_) < 4) ? (xl + (size_t)(c_) * 8 * NW) \
                                     : (xr + (size_t)((c_) - 4) * 8 * NW); \
        v0_ = *(const float4*)(s_ + (size_t)krow * NW + wcol); \
        v1_ = *(const float4*)(s_ + (size_t)(krow + 4) * NW + wcol); \
    } while (0)

    // split + store into xs[buf]
    #define STCHUNK(buf_, v0_, v1_) do { \
        float4* d0_ = (float4*)&xs[buf_][krow * PX + wcol]; \
        float4* d1_ = (float4*)&xs[buf_][(krow + 4) * PX + wcol]; \
        uint32_t hx_, hy_, hz_, hw_; \
        hx_ = tf32_hi(v0_.x); hy_ = tf32_hi(v0_.y); hz_ = tf32_hi(v0_.z); hw_ = tf32_hi(v0_.w); \
        d0_[0] = make_float4(__uint_as_float(hx_), tf32_lo(v0_.x, hx_), \
                             __uint_as_float(hy_), tf32_lo(v0_.y, hy_)); \
        d0_[1] = make_float4(__uint_as_float(hz_), tf32_lo(v0_.z, hz_), \
                             __uint_as_float(hw_), tf32_lo(v0_.w, hw_)); \
        hx_ = tf32_hi(v1_.x); hy_ = tf32_hi(v1_.y); hz_ = tf32_hi(v1_.z); hw_ = tf32_hi(v1_.w); \
        d1_[0] = make_float4(__uint_as_float(hx_), tf32_lo(v1_.x, hx_), \
                             __uint_as_float(hy_), tf32_lo(v1_.y, hy_)); \
        d1_[1] = make_float4(__uint_as_float(hz_), tf32_lo(v1_.z, hz_), \
                             __uint_as_float(hw_), tf32_lo(v1_.w, hw_)); \
    } while (0)

    float acc[2][4][4];
    #pragma unroll
    for (int mt = 0; mt < 2; mt++)
        #pragma unroll
        for (int nt = 0; nt < 4; nt++)
            #pragma unroll
            for (int r = 0; r < 4; r++) acc[mt][nt][r] = 0.f;

    {
        float4 u0, u1;
        LDCHUNK(0, u0, u1);
        STCHUNK(0, u0, u1);
    }
    __syncthreads();

    #pragma unroll 1
    for (int ks = 0; ks < 8; ks++) {
        float4 w0, w1;
        if (ks < 7) LDCHUNK(ks + 1, w0, w1);

        const float2* xb = xs[ks & 1];

        // A(=W) fragments: hi+lo via 2 LDS.128 per mtile
        uint32_t ah[2][4], al[2][4];
        #pragma unroll
        for (int mt = 0; mt < 2; mt++) {
            float4 la = wA[(g + 16 * mt) * PA + ks * 4 + tig];
            float4 lb = wA[(g + 8 + 16 * mt) * PA + ks * 4 + tig];
            ah[mt][0] = __float_as_uint(la.x); ah[mt][1] = __float_as_uint(lb.x);
            ah[mt][2] = __float_as_uint(la.z); ah[mt][3] = __float_as_uint(lb.z);
            al[mt][0] = __float_as_uint(la.y); al[mt][1] = __float_as_uint(lb.y);
            al[mt][2] = __float_as_uint(la.w); al[mt][3] = __float_as_uint(lb.w);
        }

        #pragma unroll
        for (int nt = 0; nt < 4; nt++) {
            // B(=x) fragments: hi+lo via 2 LDS.64.
            // FIX (R9 bug): this warp's worlds start at warp*32.
            float2 f0 = xb[tig * PX + warp * 32 + nt * 8 + g];
            float2 f1 = xb[(tig + 4) * PX + warp * 32 + nt * 8 + g];
            uint32_t bh0 = __float_as_uint(f0.x), bh1 = __float_as_uint(f1.x);
            uint32_t bl0 = __float_as_uint(f0.y), bl1 = __float_as_uint(f1.y);
            #pragma unroll
            for (int mt = 0; mt < 2; mt++) {
                HMMA(acc[mt][nt], ah[mt][0], ah[mt][1], ah[mt][2], ah[mt][3], bh0, bh1);
                HMMA(acc[mt][nt], al[mt][0], al[mt][1], al[mt][2], al[mt][3], bh0, bh1);
                HMMA(acc[mt][nt], ah[mt][0], ah[mt][1], ah[mt][2], ah[mt][3], bl0, bl1);
            }
        }

        if (ks < 7) STCHUNK((ks + 1) & 1, w0, w1);
        __syncthreads();
    }

    // --- epilogue: bias, L2-norm over d (g-shuffles), scale, STG.64 ---
    float bv0[2], bv1[2];
    #pragma unroll
    for (int mt = 0; mt < 2; mt++) {
        bv0[mt] = bsh[g + 16 * mt];
        bv1[mt] = bsh[g + 8 + 16 * mt];
    }

    float sq[4][2];   // [nt][world col j]
    #pragma unroll
    for (int nt = 0; nt < 4; nt++) {
        float s0 = 0.f, s1 = 0.f;
        #pragma unroll
        for (int mt = 0; mt < 2; mt++) {
            float y0 = acc[mt][nt][0] + bv0[mt];
            float y1 = acc[mt][nt][1] + bv0[mt];
            float y2 = acc[mt][nt][2] + bv1[mt];
            float y3 = acc[mt][nt][3] + bv1[mt];
            acc[mt][nt][0] = y0; acc[mt][nt][1] = y1;
            acc[mt][nt][2] = y2; acc[mt][nt][3] = y3;
            s0 = fmaf(y0, y0, fmaf(y2, y2, s0));
            s1 = fmaf(y1, y1, fmaf(y3, y3, s1));
        }
        sq[nt][0] = s0;
        sq[nt][1] = s1;
    }
    #pragma unroll
    for (int nt = 0; nt < 4; nt++) {
        #pragma unroll
        for (int j = 0; j < 2; j++) {
            float s = sq[nt][j];
            s += __shfl_xor_sync(0xffffffffu, s, 4);
            s += __shfl_xor_sync(0xffffffffu, s, 8);
            s += __shfl_xor_sync(0xffffffffu, s, 16);
            sq[nt][j] = rsqrtf(fmaxf(s, 1e-12f));
        }
    }

    float* outb = out + (size_t)idx * (DW * NW) + q * 128 + warp * 32;
    #pragma unroll
    for (int nt = 0; nt < 4; nt++) {
        const int wb = nt * 8 + 2 * tig;
        const float r0 = sq[nt][0], r1 = sq[nt][1];
        #pragma unroll
        for (int mt = 0; mt < 2; mt++) {
            float2 o0 = make_float2(acc[mt][nt][0] * r0, acc[mt][nt][1] * r1);
            float2 o1 = make_float2(acc[mt][nt][2] * r0, acc[mt][nt][3] * r1);
            *(float2*)(outb + (size_t)(g + 16 * mt) * NW + wb)     = o0;
            *(float2*)(outb + (size_t)(g + 8 + 16 * mt) * NW + wb) = o1;
        }
    }
}

extern "C" void kernel_launch(void* const* d_in, const int* in_sizes, int n_in,
                              void* d_out, int out_size) {
    const float* states  = (const float*)d_in[0];
    const float* W       = (const float*)d_in[1];
    const float* b       = (const float*)d_in[2];
    const int*   indices = (const int*)d_in[3];
    const int*   symbols = (const int*)d_in[4];
    const int*   args    = (const int*)d_in[5];
    float*       out     = (float*)d_out;

    binop_mma_kernel<<<BATCH * 4, 128>>>(states, W, b, indices, symbols, args, out);
}

// round 11
// speedup vs baseline: 1.4648x; 1.4648x over previous
#include <cuda_runtime.h>
#include <stdint.h>

#define DW    32
#define K2D   64
#define NW    512
#define BATCH 2048
#define WPAD  68     // W smem pitch (floats): banks 4g+tig distinct -> conflict-free
#define XP    136    // x stage pitch (floats), ==8 mod 32: frag banks 8*tig+g distinct

__device__ __forceinline__ uint32_t tf32_hi(float x) {
    uint32_t r; asm("cvt.rna.tf32.f32 %0, %1;" : "=r"(r) : "f"(x)); return r;
}

// D += A(tf32) * B(tf32), m16n8k8, A row-major, B col-major
#define HMMA(d, A0, A1, A2, A3, B0, B1) \
    asm volatile("mma.sync.aligned.m16n8k8.row.col.f32.tf32.tf32.f32 " \
        "{%0,%1,%2,%3}, {%4,%5,%6,%7}, {%8,%9}, {%0,%1,%2,%3};" \
        : "+f"((d)[0]), "+f"((d)[1]), "+f"((d)[2]), "+f"((d)[3]) \
        : "r"(A0), "r"(A1), "r"(A2), "r"(A3), "r"(B0), "r"(B1))

__global__ __launch_bounds__(128, 6)
void binop_mma_kernel(const float* __restrict__ states,   // [8*2048, 32, 512]
                      const float* __restrict__ W,        // [128, 32, 64]
                      const float* __restrict__ b,        // [128, 32]
                      const int*   __restrict__ indices,  // [2048]
                      const int*   __restrict__ symbols,  // [2048]
                      const int*   __restrict__ args,     // [2048, 2]
                      float*       __restrict__ out)      // [2048, 32, 512]
{
    __shared__ float wh[DW * WPAD];                  // tf32-hi of W[sym]
    __shared__ float wl[DW * WPAD];                  // tf32 of residual
    __shared__ float bsh[DW];
    __shared__ __align__(16) float xstg[2][8 * XP];  // raw fp32 x chunks, 8.7 KB

    const int n    = blockIdx.x >> 2;     // sample
    const int q    = blockIdx.x & 3;      // world-quarter (128 worlds)
    const int t    = threadIdx.x;
    const int lane = t & 31;
    const int warp = t >> 5;
    const int g    = lane >> 2;
    const int tig  = lane & 3;

    const int idx = indices[n];
    const int sym = symbols[n];
    const int a0  = args[2 * n];
    const int a1  = args[2 * n + 1];

    // --- W[sym] hi/lo split into padded smem (as R8) ---
    const float* Wp = W + (size_t)sym * (DW * K2D);
    #pragma unroll
    for (int i = 0; i < 16; i++) {
        int j  = t + 128 * i;
        int d  = j >> 6;
        int kk = j & 63;
        float w  = Wp[j];
        uint32_t h = tf32_hi(w);
        float lo = w - __uint_as_float(h);
        wh[d * WPAD + kk] = __uint_as_float(h);
        wl[d * WPAD + kk] = __uint_as_float(tf32_hi(lo));
    }
    if (t < DW) bsh[t] = b[sym * DW + t];

    // x bases for this CTA's 128-world slice
    const float* xl = states + (size_t)(a0 * BATCH + idx) * (DW * NW) + q * 128;
    const float* xr = states + (size_t)(a1 * BATCH + idx) * (DW * NW) + q * 128;

    const int srow = t >> 4;           // staging row within chunk (0..7)
    const int scol = 4 * (t & 15);     // staging col (floats)

    // stage chunk 0 (k rows 0..7, left)
    {
        const float* s = xl + (size_t)srow * NW;
        *(float4*)&xstg[0][srow * XP + scol]      = *(const float4*)(s + scol);
        *(float4*)&xstg[0][srow * XP + scol + 64] = *(const float4*)(s + scol + 64);
    }
    __syncthreads();

    float acc[2][4][4];
    #pragma unroll
    for (int mt = 0; mt < 2; mt++)
        #pragma unroll
        for (int nt = 0; nt < 4; nt++)
            #pragma unroll
            for (int r = 0; r < 4; r++) acc[mt][nt][r] = 0.f;

    const int fb = warp * 32 + g;      // fragment col base in staged chunk

    #pragma unroll
    for (int ks = 0; ks < 8; ks++) {
        // prefetch next chunk into regs (compile-time addressing via full unroll)
        float4 v0, v1;
        if (ks < 7) {
            const float* s = (ks + 1 < 4)
                ? (xl + (size_t)(8 * (ks + 1) + srow) * NW)
                : (xr + (size_t)(8 * (ks - 3) + srow) * NW);
            v0 = *(const float4*)(s + scol);
            v1 = *(const float4*)(s + scol + 64);
        }

        const float* xb = xstg[ks & 1];

        // A(=x) fragments from smem (conflict-free LDS.32), split hi/lo in regs
        uint32_t ah[2][4], al[2][4];
        #pragma unroll
        for (int mt = 0; mt < 2; mt++) {
            float f0 = xb[tig * XP + fb + 16 * mt];           // row tig,   col +0
            float f1 = xb[tig * XP + fb + 16 * mt + 8];       // row tig,   col +8
            float f2 = xb[(tig + 4) * XP + fb + 16 * mt];     // row tig+4, col +0
            float f3 = xb[(tig + 4) * XP + fb + 16 * mt + 8]; // row tig+4, col +8
            uint32_t h0 = tf32_hi(f0), h1 = tf32_hi(f1), h2 = tf32_hi(f2), h3 = tf32_hi(f3);
            ah[mt][0] = h0; ah[mt][1] = h1; ah[mt][2] = h2; ah[mt][3] = h3;
            al[mt][0] = tf32_hi(f0 - __uint_as_float(h0));
            al[mt][1] = tf32_hi(f1 - __uint_as_float(h1));
            al[mt][2] = tf32_hi(f2 - __uint_as_float(h2));
            al[mt][3] = tf32_hi(f3 - __uint_as_float(h3));
        }

        // B(=W) loads + 3xTF32 HMMA (R8-verbatim pattern)
        #pragma unroll
        for (int nt = 0; nt < 4; nt++) {
            const float* wp_ = wh + (nt * 8 + g) * WPAD + ks * 8 + tig;
            const float* lp_ = wl + (nt * 8 + g) * WPAD + ks * 8 + tig;
            uint32_t bh0 = __float_as_uint(wp_[0]);
            uint32_t bh1 = __float_as_uint(wp_[4]);
            uint32_t bl0 = __float_as_uint(lp_[0]);
            uint32_t bl1 = __float_as_uint(lp_[4]);
            #pragma unroll
            for (int mt = 0; mt < 2; mt++) {
                HMMA(acc[mt][nt], ah[mt][0], ah[mt][1], ah[mt][2], ah[mt][3], bh0, bh1);
                HMMA(acc[mt][nt], al[mt][0], al[mt][1], al[mt][2], al[mt][3], bh0, bh1);
                HMMA(acc[mt][nt], ah[mt][0], ah[mt][1], ah[mt][2], ah[mt][3], bl0, bl1);
            }
        }

        // store prefetched chunk into the other buffer
        if (ks < 7) {
            float* d = &xstg[(ks + 1) & 1][srow * XP];
            *(float4*)(d + scol)      = v0;
            *(float4*)(d + scol + 64) = v1;
            __syncthreads();
        }
    }

    // --- epilogue: bias, L2-norm over d (quad shuffles), scale, store (R8) ---
    float2 bb[4];
    #pragma unroll
    for (int nt = 0; nt < 4; nt++)
        bb[nt] = *(const float2*)&bsh[nt * 8 + 2 * tig];

    const int colA = q * 128 + warp * 32 + g;
    float* outb = out + (size_t)idx * (DW * NW);

    #pragma unroll
    for (int mt = 0; mt < 2; mt++) {
        float s0 = 0.f, s1 = 0.f;    // world cols g, g+8 of this mtile
        #pragma unroll
        for (int nt = 0; nt < 4; nt++) {
            float y0 = acc[mt][nt][0] + bb[nt].x;
            float y1 = acc[mt][nt][1] + bb[nt].y;
            float y2 = acc[mt][nt][2] + bb[nt].x;
            float y3 = acc[mt][nt][3] + bb[nt].y;
            acc[mt][nt][0] = y0; acc[mt][nt][1] = y1;
            acc[mt][nt][2] = y2; acc[mt][nt][3] = y3;
            s0 = fmaf(y0, y0, fmaf(y1, y1, s0));
            s1 = fmaf(y2, y2, fmaf(y3, y3, s1));
        }
        s0 += __shfl_xor_sync(0xffffffffu, s0, 1);
        s0 += __shfl_xor_sync(0xffffffffu, s0, 2);
        s1 += __shfl_xor_sync(0xffffffffu, s1, 1);
        s1 += __shfl_xor_sync(0xffffffffu, s1, 2);
        const float r0 = rsqrtf(fmaxf(s0, 1e-12f));
        const float r1 = rsqrtf(fmaxf(s1, 1e-12f));

        float* op = outb + colA + mt * 16;
        #pragma unroll
        for (int nt = 0; nt < 4; nt++) {
            const int nrow = nt * 8 + 2 * tig;
            op[(size_t)nrow * NW]           = acc[mt][nt][0] * r0;
            op[(size_t)(nrow + 1) * NW]     = acc[mt][nt][1] * r0;
            op[(size_t)nrow * NW + 8]       = acc[mt][nt][2] * r1;
            op[(size_t)(nrow + 1) * NW + 8] = acc[mt][nt][3] * r1;
        }
    }
}

extern "C" void kernel_launch(void* const* d_in, const int* in_sizes, int n_in,
                              void* d_out, int out_size) {
    const float* states  = (const float*)d_in[0];
    const float* W       = (const float*)d_in[1];
    const float* b       = (const float*)d_in[2];
    const int*   indices = (const int*)d_in[3];
    const int*   symbols = (const int*)d_in[4];
    const int*   args    = (const int*)d_in[5];
    float*       out     = (float*)d_out;

    binop_mma_kernel<<<BATCH * 4, 128>>>(states, W, b, indices, symbols, args, out);
}

// round 12
// speedup vs baseline: 1.7833x; 1.2175x over previous
#include <cuda_runtime.h>
#include <stdint.h>

#define DW    32
#define K2D   64
#define NW    512
#define BATCH 2048
#define WPAD  68     // W smem pitch (floats): banks 4g+tig distinct -> conflict-free
#define XP    136    // x stage pitch (floats), ==8 mod 32: frag banks 8*tig+g distinct

__device__ __forceinline__ uint32_t tf32_rna(float x) {
    uint32_t r; asm("cvt.rna.tf32.f32 %0, %1;" : "=r"(r) : "f"(x)); return r;
}

// D += A(tf32) * B(tf32), m16n8k8, A row-major, B col-major
#define HMMA(d, A0, A1, A2, A3, B0, B1) \
    asm volatile("mma.sync.aligned.m16n8k8.row.col.f32.tf32.tf32.f32 " \
        "{%0,%1,%2,%3}, {%4,%5,%6,%7}, {%8,%9}, {%0,%1,%2,%3};" \
        : "+f"((d)[0]), "+f"((d)[1]), "+f"((d)[2]), "+f"((d)[3]) \
        : "r"(A0), "r"(A1), "r"(A2), "r"(A3), "r"(B0), "r"(B1))

__global__ __launch_bounds__(128, 8)
void binop_mma_kernel(const float* __restrict__ states,   // [8*2048, 32, 512]
                      const float* __restrict__ W,        // [128, 32, 64]
                      const float* __restrict__ b,        // [128, 32]
                      const int*   __restrict__ indices,  // [2048]
                      const int*   __restrict__ symbols,  // [2048]
                      const int*   __restrict__ args,     // [2048, 2]
                      float*       __restrict__ out)      // [2048, 32, 512]
{
    __shared__ float wh[DW * WPAD];                  // tf32(W[sym]), 8.7 KB
    __shared__ float bsh[DW];
    __shared__ __align__(16) float xstg[2][8 * XP];  // raw fp32 x chunks, 8.7 KB

    const int n    = blockIdx.x >> 2;     // sample
    const int q    = blockIdx.x & 3;      // world-quarter (128 worlds)
    const int t    = threadIdx.x;
    const int lane = t & 31;
    const int warp = t >> 5;
    const int g    = lane >> 2;
    const int tig  = lane & 3;

    const int idx = indices[n];
    const int sym = symbols[n];
    const int a0  = args[2 * n];
    const int a1  = args[2 * n + 1];

    // --- tf32(W[sym]) into padded smem ---
    const float* Wp = W + (size_t)sym * (DW * K2D);
    #pragma unroll
    for (int i = 0; i < 16; i++) {
        int j  = t + 128 * i;
        int d  = j >> 6;
        int kk = j & 63;
        wh[d * WPAD + kk] = __uint_as_float(tf32_rna(Wp[j]));
    }
    if (t < DW) bsh[t] = b[sym * DW + t];

    // x bases for this CTA's 128-world slice
    const float* xl = states + (size_t)(a0 * BATCH + idx) * (DW * NW) + q * 128;
    const float* xr = states + (size_t)(a1 * BATCH + idx) * (DW * NW) + q * 128;

    const int srow = t >> 4;           // staging row within chunk (0..7)
    const int scol = 4 * (t & 15);     // staging col (floats)

    // stage chunk 0 (k rows 0..7, left)
    {
        const float* s = xl + (size_t)srow * NW;
        *(float4*)&xstg[0][srow * XP + scol]      = *(const float4*)(s + scol);
        *(float4*)&xstg[0][srow * XP + scol + 64] = *(const float4*)(s + scol + 64);
    }
    __syncthreads();

    float acc[2][4][4];
    #pragma unroll
    for (int mt = 0; mt < 2; mt++)
        #pragma unroll
        for (int nt = 0; nt < 4; nt++)
            #pragma unroll
            for (int r = 0; r < 4; r++) acc[mt][nt][r] = 0.f;

    const int fb = warp * 32 + g;      // fragment col base in staged chunk

    #pragma unroll
    for (int ks = 0; ks < 8; ks++) {
        // prefetch next chunk into regs (compile-time addressing via full unroll)
        float4 v0, v1;
        if (ks < 7) {
            const float* s = (ks + 1 < 4)
                ? (xl + (size_t)(8 * (ks + 1) + srow) * NW)
                : (xr + (size_t)(8 * (ks - 3) + srow) * NW);
            v0 = *(const float4*)(s + scol);
            v1 = *(const float4*)(s + scol + 64);
        }

        const float* xb = xstg[ks & 1];

        // A(=x) fragments from smem (conflict-free LDS.32), tf32 round in regs
        uint32_t ah[2][4];
        #pragma unroll
        for (int mt = 0; mt < 2; mt++) {
            ah[mt][0] = tf32_rna(xb[tig * XP + fb + 16 * mt]);
            ah[mt][1] = tf32_rna(xb[tig * XP + fb + 16 * mt + 8]);
            ah[mt][2] = tf32_rna(xb[(tig + 4) * XP + fb + 16 * mt]);
            ah[mt][3] = tf32_rna(xb[(tig + 4) * XP + fb + 16 * mt + 8]);
        }

        // B(=W) loads + single-pass HMMA
        #pragma unroll
        for (int nt = 0; nt < 4; nt++) {
            const float* wp_ = wh + (nt * 8 + g) * WPAD + ks * 8 + tig;
            uint32_t bh0 = __float_as_uint(wp_[0]);
            uint32_t bh1 = __float_as_uint(wp_[4]);
            #pragma unroll
            for (int mt = 0; mt < 2; mt++)
                HMMA(acc[mt][nt], ah[mt][0], ah[mt][1], ah[mt][2], ah[mt][3], bh0, bh1);
        }

        // store prefetched chunk into the other buffer
        if (ks < 7) {
            float* d = &xstg[(ks + 1) & 1][srow * XP];
            *(float4*)(d + scol)      = v0;
            *(float4*)(d + scol + 64) = v1;
            __syncthreads();
        }
    }

    // --- epilogue: bias, L2-norm over d (quad shuffles), scale, store ---
    float2 bb[4];
    #pragma unroll
    for (int nt = 0; nt < 4; nt++)
        bb[nt] = *(const float2*)&bsh[nt * 8 + 2 * tig];

    const int colA = q * 128 + warp * 32 + g;
    float* outb = out + (size_t)idx * (DW * NW);

    #pragma unroll
    for (int mt = 0; mt < 2; mt++) {
        float s0 = 0.f, s1 = 0.f;    // world cols g, g+8 of this mtile
        #pragma unroll
        for (int nt = 0; nt < 4; nt++) {
            float y0 = acc[mt][nt][0] + bb[nt].x;
            float y1 = acc[mt][nt][1] + bb[nt].y;
            float y2 = acc[mt][nt][2] + bb[nt].x;
            float y3 = acc[mt][nt][3] + bb[nt].y;
            acc[mt][nt][0] = y0; acc[mt][nt][1] = y1;
            acc[mt][nt][2] = y2; acc[mt][nt][3] = y3;
            s0 = fmaf(y0, y0, fmaf(y1, y1, s0));
            s1 = fmaf(y2, y2, fmaf(y3, y3, s1));
        }
        s0 += __shfl_xor_sync(0xffffffffu, s0, 1);
        s0 += __shfl_xor_sync(0xffffffffu, s0, 2);
        s1 += __shfl_xor_sync(0xffffffffu, s1, 1);
        s1 += __shfl_xor_sync(0xffffffffu, s1, 2);
        const float r0 = rsqrtf(fmaxf(s0, 1e-12f));
        const float r1 = rsqrtf(fmaxf(s1, 1e-12f));

        float* op = outb + colA + mt * 16;
        #pragma unroll
        for (int nt = 0; nt < 4; nt++) {
            const int nrow = nt * 8 + 2 * tig;
            op[(size_t)nrow * NW]           = acc[mt][nt][0] * r0;
            op[(size_t)(nrow + 1) * NW]     = acc[mt][nt][1] * r0;
            op[(size_t)nrow * NW + 8]       = acc[mt][nt][2] * r1;
            op[(size_t)(nrow + 1) * NW + 8] = acc[mt][nt][3] * r1;
        }
    }
}

extern "C" void kernel_launch(void* const* d_in, const int* in_sizes, int n_in,
                              void* d_out, int out_size) {
    const float* states  = (const float*)d_in[0];
    const float* W       = (const float*)d_in[1];
    const float* b       = (const float*)d_in[2];
    const int*   indices = (const int*)d_in[3];
    const int*   symbols = (const int*)d_in[4];
    const int*   args    = (const int*)d_in[5];
    float*       out     = (float*)d_out;

    binop_mma_kernel<<<BATCH * 4, 128>>>(states, W, b, indices, symbols, args, out);
}

// round 14
// speedup vs baseline: 1.9454x; 1.0909x over previous
#include <cuda_runtime.h>
#include <stdint.h>

#define DW    32
#define K2D   64
#define NW    512
#define BATCH 2048
#define WPAD  68     // W smem pitch (floats): banks 4g+tig distinct -> conflict-free
#define XP    136    // x stage pitch (floats), ==8 mod 32: frag banks 8*tig+g distinct

__device__ __forceinline__ uint32_t tf32_rna(float x) {
    uint32_t r; asm("cvt.rna.tf32.f32 %0, %1;" : "=r"(r) : "f"(x)); return r;
}

// D += A(tf32) * B(tf32), m16n8k8, A row-major, B col-major
#define HMMA(d, A0, A1, A2, A3, B0, B1) \
    asm volatile("mma.sync.aligned.m16n8k8.row.col.f32.tf32.tf32.f32 " \
        "{%0,%1,%2,%3}, {%4,%5,%6,%7}, {%8,%9}, {%0,%1,%2,%3};" \
        : "+f"((d)[0]), "+f"((d)[1]), "+f"((d)[2]), "+f"((d)[3]) \
        : "r"(A0), "r"(A1), "r"(A2), "r"(A3), "r"(B0), "r"(B1))

#define CP_ASYNC16(dst_u32, src) \
    asm volatile("cp.async.cg.shared.global [%0], [%1], 16;" \
                 :: "r"(dst_u32), "l"(src) : "memory")
#define CP_COMMIT() asm volatile("cp.async.commit_group;" ::: "memory")
#define CP_WAIT1()  asm volatile("cp.async.wait_group 1;" ::: "memory")
#define CP_WAIT0()  asm volatile("cp.async.wait_group 0;" ::: "memory")

__global__ __launch_bounds__(128, 8)
void binop_mma_kernel(const float* __restrict__ states,   // [8*2048, 32, 512]
                      const float* __restrict__ W,        // [128, 32, 64]
                      const float* __restrict__ b,        // [128, 32]
                      const int*   __restrict__ indices,  // [2048]
                      const int*   __restrict__ symbols,  // [2048]
                      const int*   __restrict__ args,     // [2048, 2]
                      float*       __restrict__ out)      // [2048, 32, 512]
{
    __shared__ float wh[DW * WPAD];                      // tf32(W[sym]), 8.7 KB
    __shared__ float bsh[DW];
    __shared__ __align__(16) float xstg[3][8 * XP];      // 3-stage x ring, 13 KB

    const int n    = blockIdx.x >> 2;     // sample
    const int q    = blockIdx.x & 3;      // world-quarter (128 worlds)
    const int t    = threadIdx.x;
    const int lane = t & 31;
    const int warp = t >> 5;
    const int g    = lane >> 2;
    const int tig  = lane & 3;

    const int idx = indices[n];
    const int sym = symbols[n];
    const int a0  = args[2 * n];
    const int a1  = args[2 * n + 1];

    // x bases for this CTA's 128-world slice
    const float* xl = states + (size_t)(a0 * BATCH + idx) * (DW * NW) + q * 128;
    const float* xr = states + (size_t)(a1 * BATCH + idx) * (DW * NW) + q * 128;

    const int srow = t >> 4;           // staging row within chunk (0..7)
    const int scol = 4 * (t & 15);     // staging col (floats)

    uint32_t xsb;
    {
        void* p = (void*)&xstg[0][srow * XP + scol];
        asm("{ .reg .u64 u; cvta.to.shared.u64 u, %1; cvt.u32.u64 %0, u; }"
            : "=r"(xsb) : "l"(p));
    }

    // issue chunk c into ring slot c%3 (2x cp.async 16B per thread)
    #define ISSUE(c_) do { \
        const float* s_ = ((c_) < 4) ? (xl + (size_t)(8 * (c_) + srow) * NW) \
                                     : (xr + (size_t)(8 * ((c_) - 4) + srow) * NW); \
        uint32_t d_ = xsb + ((c_) % 3) * (8 * XP * 4); \
        CP_ASYNC16(d_,       s_ + scol); \
        CP_ASYNC16(d_ + 256, s_ + scol + 64); \
        CP_COMMIT(); \
    } while (0)

    // prologue: chunks 0,1 in flight
    ISSUE(0);
    ISSUE(1);

    // --- tf32(W[sym]) into padded smem (overlaps with async x loads) ---
    const float* Wp = W + (size_t)sym * (DW * K2D);
    #pragma unroll
    for (int i = 0; i < 16; i++) {
        int j  = t + 128 * i;
        int d  = j >> 6;
        int kk = j & 63;
        wh[d * WPAD + kk] = __uint_as_float(tf32_rna(Wp[j]));
    }
    if (t < DW) bsh[t] = b[sym * DW + t];

    float acc[2][4][4];
    #pragma unroll
    for (int mt = 0; mt < 2; mt++)
        #pragma unroll
        for (int nt = 0; nt < 4; nt++)
            #pragma unroll
            for (int r = 0; r < 4; r++) acc[mt][nt][r] = 0.f;

    const int fb = warp * 32 + g;      // fragment col base in staged chunk

    #pragma unroll
    for (int ks = 0; ks < 8; ks++) {
        // Drain rule (R13 bugfix): for ks<7 "<=1 pending" proves chunk ks
        // landed; at ks==7 the single pending group IS chunk 7 -> full drain.
        if (ks < 7) CP_WAIT1(); else CP_WAIT0();
        __syncthreads();               // all warps done with slot (ks+2)%3's old data
        if (ks + 2 < 8) ISSUE(ks + 2);

        const float* xb = xstg[ks % 3];

        // A(=x) fragments from smem (conflict-free LDS.32), tf32 round in regs
        uint32_t ah[2][4];
        #pragma unroll
        for (int mt = 0; mt < 2; mt++) {
            ah[mt][0] = tf32_rna(xb[tig * XP + fb + 16 * mt]);
            ah[mt][1] = tf32_rna(xb[tig * XP + fb + 16 * mt + 8]);
            ah[mt][2] = tf32_rna(xb[(tig + 4) * XP + fb + 16 * mt]);
            ah[mt][3] = tf32_rna(xb[(tig + 4) * XP + fb + 16 * mt + 8]);
        }

        // B(=W) loads + single-pass HMMA
        #pragma unroll
        for (int nt = 0; nt < 4; nt++) {
            const float* wp_ = wh + (nt * 8 + g) * WPAD + ks * 8 + tig;
            uint32_t bh0 = __float_as_uint(wp_[0]);
            uint32_t bh1 = __float_as_uint(wp_[4]);
            #pragma unroll
            for (int mt = 0; mt < 2; mt++)
                HMMA(acc[mt][nt], ah[mt][0], ah[mt][1], ah[mt][2], ah[mt][3], bh0, bh1);
        }
    }

    // --- epilogue: bias, L2-norm over d (quad shuffles), scale, store ---
    float2 bb[4];
    #pragma unroll
    for (int nt = 0; nt < 4; nt++)
        bb[nt] = *(const float2*)&bsh[nt * 8 + 2 * tig];

    const int colA = q * 128 + warp * 32 + g;
    float* outb = out + (size_t)idx * (DW * NW);

    #pragma unroll
    for (int mt = 0; mt < 2; mt++) {
        float s0 = 0.f, s1 = 0.f;    // world cols g, g+8 of this mtile
        #pragma unroll
        for (int nt = 0; nt < 4; nt++) {
            float y0 = acc[mt][nt][0] + bb[nt].x;
            float y1 = acc[mt][nt][1] + bb[nt].y;
            float y2 = acc[mt][nt][2] + bb[nt].x;
            float y3 = acc[mt][nt][3] + bb[nt].y;
            acc[mt][nt][0] = y0; acc[mt][nt][1] = y1;
            acc[mt][nt][2] = y2; acc[mt][nt][3] = y3;
            s0 = fmaf(y0, y0, fmaf(y1, y1, s0));
            s1 = fmaf(y2, y2, fmaf(y3, y3, s1));
        }
        s0 += __shfl_xor_sync(0xffffffffu, s0, 1);
        s0 += __shfl_xor_sync(0xffffffffu, s0, 2);
        s1 += __shfl_xor_sync(0xffffffffu, s1, 1);
        s1 += __shfl_xor_sync(0xffffffffu, s1, 2);
        const float r0 = rsqrtf(fmaxf(s0, 1e-12f));
        const float r1 = rsqrtf(fmaxf(s1, 1e-12f));

        float* op = outb + colA + mt * 16;
        #pragma unroll
        for (int nt = 0; nt < 4; nt++) {
            const int nrow = nt * 8 + 2 * tig;
            op[(size_t)nrow * NW]           = acc[mt][nt][0] * r0;
            op[(size_t)(nrow + 1) * NW]     = acc[mt][nt][1] * r0;
            op[(size_t)nrow * NW + 8]       = acc[mt][nt][2] * r1;
            op[(size_t)(nrow + 1) * NW + 8] = acc[mt][nt][3] * r1;
        }
    }
}

extern "C" void kernel_launch(void* const* d_in, const int* in_sizes, int n_in,
                              void* d_out, int out_size) {
    const float* states  = (const float*)d_in[0];
    const float* W       = (const float*)d_in[1];
    const float* b       = (const float*)d_in[2];
    const int*   indices = (const int*)d_in[3];
    const int*   symbols = (const int*)d_in[4];
    const int*   args    = (const int*)d_in[5];
    float*       out     = (float*)d_out;

    binop_mma_kernel<<<BATCH * 4, 128>>>(states, W, b, indices, symbols, args, out);
}

// round 15
// speedup vs baseline: 1.9920x; 1.0240x over previous
#include <cuda_runtime.h>
#include <stdint.h>

#define DW    32
#define K2D   64
#define NW    512
#define BATCH 2048
#define WPAD  68     // W smem pitch (floats): banks 4g+tig distinct -> conflict-free
#define XP    136    // x stage pitch (floats), ==8 mod 32: frag banks 8*tig+g distinct
#define TP    132    // transpose buffer pitch (floats), ==4 mod 32

__device__ __forceinline__ uint32_t tf32_rna(float x) {
    uint32_t r; asm("cvt.rna.tf32.f32 %0, %1;" : "=r"(r) : "f"(x)); return r;
}

// D += A(tf32) * B(tf32), m16n8k8, A row-major, B col-major
#define HMMA(d, A0, A1, A2, A3, B0, B1) \
    asm volatile("mma.sync.aligned.m16n8k8.row.col.f32.tf32.tf32.f32 " \
        "{%0,%1,%2,%3}, {%4,%5,%6,%7}, {%8,%9}, {%0,%1,%2,%3};" \
        : "+f"((d)[0]), "+f"((d)[1]), "+f"((d)[2]), "+f"((d)[3]) \
        : "r"(A0), "r"(A1), "r"(A2), "r"(A3), "r"(B0), "r"(B1))

#define CP_ASYNC16(dst_u32, src) \
    asm volatile("cp.async.cg.shared.global [%0], [%1], 16;" \
                 :: "r"(dst_u32), "l"(src) : "memory")
#define CP_COMMIT() asm volatile("cp.async.commit_group;" ::: "memory")
#define CP_WAIT1()  asm volatile("cp.async.wait_group 1;" ::: "memory")
#define CP_WAIT0()  asm volatile("cp.async.wait_group 0;" ::: "memory")

__global__ __launch_bounds__(128, 8)
void binop_mma_kernel(const float* __restrict__ states,   // [8*2048, 32, 512]
                      const float* __restrict__ W,        // [128, 32, 64]
                      const float* __restrict__ b,        // [128, 32]
                      const int*   __restrict__ indices,  // [2048]
                      const int*   __restrict__ symbols,  // [2048]
                      const int*   __restrict__ args,     // [2048, 2]
                      float*       __restrict__ out)      // [2048, 32, 512]
{
    __shared__ float wh[DW * WPAD];                      // tf32(W[sym]), 8.7 KB
    __shared__ float bsh[DW];
    __shared__ __align__(16) float xstg[3][8 * XP];      // 3-stage x ring, 13 KB
                                                         // (reused as 16xTP transpose buf)

    const int n    = blockIdx.x >> 2;     // sample
    const int q    = blockIdx.x & 3;      // world-quarter (128 worlds)
    const int t    = threadIdx.x;
    const int lane = t & 31;
    const int warp = t >> 5;
    const int g    = lane >> 2;
    const int tig  = lane & 3;

    const int idx = indices[n];
    const int sym = symbols[n];
    const int a0  = args[2 * n];
    const int a1  = args[2 * n + 1];

    // x bases for this CTA's 128-world slice
    const float* xl = states + (size_t)(a0 * BATCH + idx) * (DW * NW) + q * 128;
    const float* xr = states + (size_t)(a1 * BATCH + idx) * (DW * NW) + q * 128;

    const int srow = t >> 4;           // staging row within chunk (0..7)
    const int scol = 4 * (t & 15);     // staging col (floats)

    uint32_t xsb;
    {
        void* p = (void*)&xstg[0][srow * XP + scol];
        asm("{ .reg .u64 u; cvta.to.shared.u64 u, %1; cvt.u32.u64 %0, u; }"
            : "=r"(xsb) : "l"(p));
    }

    // issue chunk c into ring slot c%3 (2x cp.async 16B per thread)
    #define ISSUE(c_) do { \
        const float* s_ = ((c_) < 4) ? (xl + (size_t)(8 * (c_) + srow) * NW) \
                                     : (xr + (size_t)(8 * ((c_) - 4) + srow) * NW); \
        uint32_t d_ = xsb + ((c_) % 3) * (8 * XP * 4); \
        CP_ASYNC16(d_,       s_ + scol); \
        CP_ASYNC16(d_ + 256, s_ + scol + 64); \
        CP_COMMIT(); \
    } while (0)

    // prologue: chunks 0,1 in flight
    ISSUE(0);
    ISSUE(1);

    // --- tf32(W[sym]) into padded smem (overlaps with async x loads) ---
    const float* Wp = W + (size_t)sym * (DW * K2D);
    #pragma unroll
    for (int i = 0; i < 16; i++) {
        int j  = t + 128 * i;
        int d  = j >> 6;
        int kk = j & 63;
        wh[d * WPAD + kk] = __uint_as_float(tf32_rna(Wp[j]));
    }
    if (t < DW) bsh[t] = b[sym * DW + t];

    float acc[2][4][4];
    #pragma unroll
    for (int mt = 0; mt < 2; mt++)
        #pragma unroll
        for (int nt = 0; nt < 4; nt++)
            #pragma unroll
            for (int r = 0; r < 4; r++) acc[mt][nt][r] = 0.f;

    const int fb = warp * 32 + g;      // fragment col base in staged chunk

    #pragma unroll
    for (int ks = 0; ks < 8; ks++) {
        // Drain rule: ks<7 -> "<=1 pending" proves chunk ks landed;
        // ks==7 -> the single pending group IS chunk 7 -> full drain.
        if (ks < 7) CP_WAIT1(); else CP_WAIT0();
        __syncthreads();               // all warps done with slot (ks+2)%3's old data
        if (ks + 2 < 8) ISSUE(ks + 2);

        const float* xb = xstg[ks % 3];

        // A(=x) fragments from smem (conflict-free LDS.32), tf32 round in regs
        uint32_t ah[2][4];
        #pragma unroll
        for (int mt = 0; mt < 2; mt++) {
            ah[mt][0] = tf32_rna(xb[tig * XP + fb + 16 * mt]);
            ah[mt][1] = tf32_rna(xb[tig * XP + fb + 16 * mt + 8]);
            ah[mt][2] = tf32_rna(xb[(tig + 4) * XP + fb + 16 * mt]);
            ah[mt][3] = tf32_rna(xb[(tig + 4) * XP + fb + 16 * mt + 8]);
        }

        // B(=W) loads + single-pass HMMA
        #pragma unroll
        for (int nt = 0; nt < 4; nt++) {
            const float* wp_ = wh + (nt * 8 + g) * WPAD + ks * 8 + tig;
            uint32_t bh0 = __float_as_uint(wp_[0]);
            uint32_t bh1 = __float_as_uint(wp_[4]);
            #pragma unroll
            for (int mt = 0; mt < 2; mt++)
                HMMA(acc[mt][nt], ah[mt][0], ah[mt][1], ah[mt][2], ah[mt][3], bh0, bh1);
        }
    }

    // --- epilogue: bias, L2-norm over d (quad shuffles), scale ---
    float2 bb[4];
    #pragma unroll
    for (int nt = 0; nt < 4; nt++)
        bb[nt] = *(const float2*)&bsh[nt * 8 + 2 * tig];

    #pragma unroll
    for (int mt = 0; mt < 2; mt++) {
        float s0 = 0.f, s1 = 0.f;    // world cols g, g+8 of this mtile
        #pragma unroll
        for (int nt = 0; nt < 4; nt++) {
            float y0 = acc[mt][nt][0] + bb[nt].x;
            float y1 = acc[mt][nt][1] + bb[nt].y;
            float y2 = acc[mt][nt][2] + bb[nt].x;
            float y3 = acc[mt][nt][3] + bb[nt].y;
            acc[mt][nt][0] = y0; acc[mt][nt][1] = y1;
            acc[mt][nt][2] = y2; acc[mt][nt][3] = y3;
            s0 = fmaf(y0, y0, fmaf(y1, y1, s0));
            s1 = fmaf(y2, y2, fmaf(y3, y3, s1));
        }
        s0 += __shfl_xor_sync(0xffffffffu, s0, 1);
        s0 += __shfl_xor_sync(0xffffffffu, s0, 2);
        s1 += __shfl_xor_sync(0xffffffffu, s1, 1);
        s1 += __shfl_xor_sync(0xffffffffu, s1, 2);
        const float r0 = rsqrtf(fmaxf(s0, 1e-12f));
        const float r1 = rsqrtf(fmaxf(s1, 1e-12f));
        #pragma unroll
        for (int nt = 0; nt < 4; nt++) {
            acc[mt][nt][0] *= r0;
            acc[mt][nt][1] *= r0;
            acc[mt][nt][2] *= r1;
            acc[mt][nt][3] *= r1;
        }
    }

    // --- store via smem transpose -> coalesced STG.128 ---
    // Reuse the (now dead) x ring as a 16 x TP float buffer; two passes of
    // 16 d-rows each (pass p covers nt = 2p, 2p+1).
    float* tb = &xstg[0][0];
    float* outb = out + (size_t)idx * (DW * NW) + q * 128;

    const int trow = t >> 3;           // reader: row (0..15)
    const int tcol = 4 * (t & 7);      // reader: float4 col base

    #pragma unroll
    for (int p = 0; p < 2; p++) {
        __syncthreads();               // buffer free (mainloop or previous pass done)
        #pragma unroll
        for (int nn = 0; nn < 2; nn++) {
            const int nt = 2 * p + nn;
            const int rl = nn * 8 + 2 * tig;            // local row in this pass
            const int cb = warp * 32 + g;
            // banks: 4*rl + cb ≡ 8*tig + g + const (mod 32) -> conflict-free
            tb[rl * TP + cb]            = acc[0][nt][0];
            tb[(rl + 1) * TP + cb]      = acc[0][nt][1];
            tb[rl * TP + cb + 8]        = acc[0][nt][2];
            tb[(rl + 1) * TP + cb + 8]  = acc[0][nt][3];
            tb[rl * TP + cb + 16]       = acc[1][nt][0];
            tb[(rl + 1) * TP + cb + 16] = acc[1][nt][1];
            tb[rl * TP + cb + 24]       = acc[1][nt][2];
            tb[(rl + 1) * TP + cb + 24] = acc[1][nt][3];
        }
        __syncthreads();
        // read rows coalesced, store STG.128 (each 8-lane group = one 128B line)
        #pragma unroll
        for (int j = 0; j < 4; j++) {
            float4 v = *(const float4*)&tb[trow * TP + tcol + 32 * j];
            *(float4*)(outb + (size_t)(p * 16 + trow) * NW + tcol + 32 * j) = v;
        }
    }
}

extern "C" void kernel_launch(void* const* d_in, const int* in_sizes, int n_in,
                              void* d_out, int out_size) {
    const float* states  = (const float*)d_in[0];
    const float* W       = (const float*)d_in[1];
    const float* b       = (const float*)d_in[2];
    const int*   indices = (const int*)d_in[3];
    const int*   symbols = (const int*)d_in[4];
    const int*   args    = (const int*)d_in[5];
    float*       out     = (float*)d_out;

    binop_mma_kernel<<<BATCH * 4, 128>>>(states, W, b, indices, symbols, args, out);
}

// round 16
// speedup vs baseline: 1.9929x; 1.0005x over previous
#include <cuda_runtime.h>
#include <stdint.h>

#define DW    32
#define K2D   64
#define NW    512
#define BATCH 2048
#define WPAD  68     // W smem pitch (floats): banks 4g+tig distinct -> conflict-free
#define XP    136    // x stage pitch (floats), ==8 mod 32: frag banks 8*tig+g distinct
#define TP    132    // transpose buffer pitch (floats), ==4 mod 32

__device__ __forceinline__ uint32_t tf32_rna(float x) {
    uint32_t r; asm("cvt.rna.tf32.f32 %0, %1;" : "=r"(r) : "f"(x)); return r;
}

// D += A(tf32) * B(tf32), m16n8k8, A row-major, B col-major
#define HMMA(d, A0, A1, A2, A3, B0, B1) \
    asm volatile("mma.sync.aligned.m16n8k8.row.col.f32.tf32.tf32.f32 " \
        "{%0,%1,%2,%3}, {%4,%5,%6,%7}, {%8,%9}, {%0,%1,%2,%3};" \
        : "+f"((d)[0]), "+f"((d)[1]), "+f"((d)[2]), "+f"((d)[3]) \
        : "r"(A0), "r"(A1), "r"(A2), "r"(A3), "r"(B0), "r"(B1))

#define CP_ASYNC16(dst_u32, src) \
    asm volatile("cp.async.cg.shared.global [%0], [%1], 16;" \
                 :: "r"(dst_u32), "l"(src) : "memory")
#define CP_COMMIT() asm volatile("cp.async.commit_group;" ::: "memory")
#define CP_WAIT2()  asm volatile("cp.async.wait_group 2;" ::: "memory")
#define CP_WAIT1()  asm volatile("cp.async.wait_group 1;" ::: "memory")
#define CP_WAIT0()  asm volatile("cp.async.wait_group 0;" ::: "memory")

__global__ __launch_bounds__(128, 8)
void binop_mma_kernel(const float* __restrict__ states,   // [8*2048, 32, 512]
                      const float* __restrict__ W,        // [128, 32, 64]
                      const float* __restrict__ b,        // [128, 32]
                      const int*   __restrict__ indices,  // [2048]
                      const int*   __restrict__ symbols,  // [2048]
                      const int*   __restrict__ args,     // [2048, 2]
                      float*       __restrict__ out)      // [2048, 32, 512]
{
    __shared__ float wh[DW * WPAD];                      // tf32(W[sym]), 8.7 KB
    __shared__ float bsh[DW];
    __shared__ __align__(16) float xstg[4][8 * XP];      // 4-stage x ring, 17.4 KB
                                                         // (reused as 32xTP transpose buf)

    const int n    = blockIdx.x >> 2;     // sample
    const int q    = blockIdx.x & 3;      // world-quarter (128 worlds)
    const int t    = threadIdx.x;
    const int lane = t & 31;
    const int warp = t >> 5;
    const int g    = lane >> 2;
    const int tig  = lane & 3;

    const int idx = indices[n];
    const int sym = symbols[n];
    const int a0  = args[2 * n];
    const int a1  = args[2 * n + 1];

    // x bases for this CTA's 128-world slice
    const float* xl = states + (size_t)(a0 * BATCH + idx) * (DW * NW) + q * 128;
    const float* xr = states + (size_t)(a1 * BATCH + idx) * (DW * NW) + q * 128;

    const int srow = t >> 4;           // staging row within chunk (0..7)
    const int scol = 4 * (t & 15);     // staging col (floats)

    uint32_t xsb;
    {
        void* p = (void*)&xstg[0][srow * XP + scol];
        asm("{ .reg .u64 u; cvta.to.shared.u64 u, %1; cvt.u32.u64 %0, u; }"
            : "=r"(xsb) : "l"(p));
    }

    // issue chunk c into ring slot c%4 (2x cp.async 16B per thread)
    #define ISSUE(c_) do { \
        const float* s_ = ((c_) < 4) ? (xl + (size_t)(8 * (c_) + srow) * NW) \
                                     : (xr + (size_t)(8 * ((c_) - 4) + srow) * NW); \
        uint32_t d_ = xsb + ((c_) & 3) * (8 * XP * 4); \
        CP_ASYNC16(d_,       s_ + scol); \
        CP_ASYNC16(d_ + 256, s_ + scol + 64); \
        CP_COMMIT(); \
    } while (0)

    // prologue: chunks 0,1,2 in flight (depth 3)
    ISSUE(0);
    ISSUE(1);
    ISSUE(2);

    // --- tf32(W[sym]) into padded smem (overlaps with async x loads) ---
    const float* Wp = W + (size_t)sym * (DW * K2D);
    #pragma unroll
    for (int i = 0; i < 16; i++) {
        int j  = t + 128 * i;
        int d  = j >> 6;
        int kk = j & 63;
        wh[d * WPAD + kk] = __uint_as_float(tf32_rna(Wp[j]));
    }
    if (t < DW) bsh[t] = b[sym * DW + t];

    float acc[2][4][4];
    #pragma unroll
    for (int mt = 0; mt < 2; mt++)
        #pragma unroll
        for (int nt = 0; nt < 4; nt++)
            #pragma unroll
            for (int r = 0; r < 4; r++) acc[mt][nt][r] = 0.f;

    const int fb = warp * 32 + g;      // fragment col base in staged chunk

    #pragma unroll
    for (int ks = 0; ks < 8; ks++) {
        // Drain ledger: pending at top = {ks .. min(ks+2,7)} ->
        //   ks<=5: 3 pending, wait 2 proves chunk ks landed;
        //   ks==6: 2 pending, wait 1; ks==7: 1 pending, full drain.
        if (ks < 6) CP_WAIT2(); else if (ks == 6) CP_WAIT1(); else CP_WAIT0();
        __syncthreads();               // all warps done with slot (ks+3)&3's old data
        if (ks + 3 < 8) ISSUE(ks + 3);

        const float* xb = xstg[ks & 3];

        // A(=x) fragments from smem (conflict-free LDS.32), tf32 round in regs
        uint32_t ah[2][4];
        #pragma unroll
        for (int mt = 0; mt < 2; mt++) {
            ah[mt][0] = tf32_rna(xb[tig * XP + fb + 16 * mt]);
            ah[mt][1] = tf32_rna(xb[tig * XP + fb + 16 * mt + 8]);
            ah[mt][2] = tf32_rna(xb[(tig + 4) * XP + fb + 16 * mt]);
            ah[mt][3] = tf32_rna(xb[(tig + 4) * XP + fb + 16 * mt + 8]);
        }

        // B(=W) loads + single-pass HMMA
        #pragma unroll
        for (int nt = 0; nt < 4; nt++) {
            const float* wp_ = wh + (nt * 8 + g) * WPAD + ks * 8 + tig;
            uint32_t bh0 = __float_as_uint(wp_[0]);
            uint32_t bh1 = __float_as_uint(wp_[4]);
            #pragma unroll
            for (int mt = 0; mt < 2; mt++)
                HMMA(acc[mt][nt], ah[mt][0], ah[mt][1], ah[mt][2], ah[mt][3], bh0, bh1);
        }
    }

    // --- epilogue: bias, L2-norm over d (quad shuffles), scale ---
    float2 bb[4];
    #pragma unroll
    for (int nt = 0; nt < 4; nt++)
        bb[nt] = *(const float2*)&bsh[nt * 8 + 2 * tig];

    #pragma unroll
    for (int mt = 0; mt < 2; mt++) {
        float s0 = 0.f, s1 = 0.f;    // world cols g, g+8 of this mtile
        #pragma unroll
        for (int nt = 0; nt < 4; nt++) {
            float y0 = acc[mt][nt][0] + bb[nt].x;
            float y1 = acc[mt][nt][1] + bb[nt].y;
            float y2 = acc[mt][nt][2] + bb[nt].x;
            float y3 = acc[mt][nt][3] + bb[nt].y;
            acc[mt][nt][0] = y0; acc[mt][nt][1] = y1;
            acc[mt][nt][2] = y2; acc[mt][nt][3] = y3;
            s0 = fmaf(y0, y0, fmaf(y1, y1, s0));
            s1 = fmaf(y2, y2, fmaf(y3, y3, s1));
        }
        s0 += __shfl_xor_sync(0xffffffffu, s0, 1);
        s0 += __shfl_xor_sync(0xffffffffu, s0, 2);
        s1 += __shfl_xor_sync(0xffffffffu, s1, 1);
        s1 += __shfl_xor_sync(0xffffffffu, s1, 2);
        const float r0 = rsqrtf(fmaxf(s0, 1e-12f));
        const float r1 = rsqrtf(fmaxf(s1, 1e-12f));
        #pragma unroll
        for (int nt = 0; nt < 4; nt++) {
            acc[mt][nt][0] *= r0;
            acc[mt][nt][1] *= r0;
            acc[mt][nt][2] *= r1;
            acc[mt][nt][3] *= r1;
        }
    }

    // --- store via single-pass 32-row smem transpose -> coalesced STG.128 ---
    float* tb = &xstg[0][0];           // 32 x TP floats = 16.9 KB (< 17.4 KB ring)
    float* outb = out + (size_t)idx * (DW * NW) + q * 128;

    const int trow = t >> 3;           // reader: row (0..15), also handles +16
    const int tcol = 4 * (t & 7);      // reader: float4 col base

    __syncthreads();                   // mainloop consumers done with ring
    #pragma unroll
    for (int nt = 0; nt < 4; nt++) {
        const int rl = nt * 8 + 2 * tig;        // d rows rl, rl+1
        const int cb = warp * 32 + g;
        // banks: 4*rl + cb ≡ 8*tig + g + const (mod 32) -> conflict-free
        tb[rl * TP + cb]            = acc[0][nt][0];
        tb[(rl + 1) * TP + cb]      = acc[0][nt][1];
        tb[rl * TP + cb + 8]        = acc[0][nt][2];
        tb[(rl + 1) * TP + cb + 8]  = acc[0][nt][3];
        tb[rl * TP + cb + 16]       = acc[1][nt][0];
        tb[(rl + 1) * TP + cb + 16] = acc[1][nt][1];
        tb[rl * TP + cb + 24]       = acc[1][nt][2];
        tb[(rl + 1) * TP + cb + 24] = acc[1][nt][3];
    }
    __syncthreads();
    // read rows coalesced, store STG.128 (each 8-lane group = one 128B line)
    #pragma unroll
    for (int h = 0; h < 2; h++) {
        const int row = trow + 16 * h;
        #pragma unroll
        for (int j = 0; j < 4; j++) {
            float4 v = *(const float4*)&tb[row * TP + tcol + 32 * j];
            *(float4*)(outb + (size_t)row * NW + tcol + 32 * j) = v;
        }
    }
}

extern "C" void kernel_launch(void* const* d_in, const int* in_sizes, int n_in,
                              void* d_out, int out_size) {
    const float* states  = (const float*)d_in[0];
    const float* W       = (const float*)d_in[1];
    const float* b       = (const float*)d_in[2];
    const int*   indices = (const int*)d_in[3];
    const int*   symbols = (const int*)d_in[4];
    const int*   args    = (const int*)d_in[5];
    float*       out     = (float*)d_out;

    binop_mma_kernel<<<BATCH * 4, 128>>>(states, W, b, indices, symbols, args, out);
}